// round 2
// baseline (speedup 1.0000x reference)
#include <cuda_runtime.h>
#include <cstdint>
#include <cstddef>

#define SEQ    2048
#define BATCH  32
#define XSIZE  256
#define HID    512
#define MTOT   (SEQ * BATCH)          // 65536 rows for the GEMMs
#define CH     (BATCH * HID)          // 16384 independent recurrence channels
#define OUT_ELEMS (SEQ * BATCH * HID) // 33554432

// Scratch (allocation-free rule: __device__ globals).
// g_lin holds lin0, then is reused for lin1. g_y0 holds layer-0 activations.
__device__ float g_lin[OUT_ELEMS];
__device__ float g_y0[OUT_ELEMS];

// ---------------------------------------------------------------------------
// packed f32x2 helpers (sm_10x: fma.rn.f32x2 runs at full FMA-pipe rate,
// unlike 3-reg FFMA which is half rate per SASS_QUICKREF)
// ---------------------------------------------------------------------------
__device__ __forceinline__ unsigned long long pack2_dup(float v) {
    unsigned long long r;
    asm("mov.b64 %0, {%1, %1};" : "=l"(r) : "f"(v));
    return r;
}
__device__ __forceinline__ void fma2(unsigned long long &acc,
                                     unsigned long long a,
                                     unsigned long long b) {
    asm("fma.rn.f32x2 %0, %1, %2, %0;" : "+l"(acc) : "l"(a), "l"(b));
}
__device__ __forceinline__ float2 unpack2(unsigned long long v) {
    float2 f;
    asm("mov.b64 {%0, %1}, %2;" : "=f"(f.x), "=f"(f.y) : "l"(v));
    return f;
}

// ---------------------------------------------------------------------------
// SGEMM:  C[m][n] = sum_k A[m][k] * W[n][k] + bias[n]
// A: [MTOT x K] row-major.  W: [N x K] row-major (so B = W^T).  N = HID = 512.
// Tile: 128x128, BK=16, 256 threads, 8x8 per thread, double-buffered smem.
// ---------------------------------------------------------------------------
__device__ __forceinline__ void tile_mma(const float (*As)[128], const float (*Bs)[128],
                                         int tx, int ty, unsigned long long acc[8][4]) {
#pragma unroll
    for (int k = 0; k < 16; k++) {
        const float4 a0 = *(const float4*)&As[k][ty * 4];
        const float4 a1 = *(const float4*)&As[k][ty * 4 + 64];
        const ulonglong2 bq0 = *(const ulonglong2*)&Bs[k][tx * 4];
        const ulonglong2 bq1 = *(const ulonglong2*)&Bs[k][tx * 4 + 64];
        const unsigned long long bp0 = bq0.x, bp1 = bq0.y, bp2 = bq1.x, bp3 = bq1.y;
        const float av[8] = {a0.x, a0.y, a0.z, a0.w, a1.x, a1.y, a1.z, a1.w};
#pragma unroll
        for (int i = 0; i < 8; i++) {
            const unsigned long long ap = pack2_dup(av[i]);
            fma2(acc[i][0], ap, bp0);
            fma2(acc[i][1], ap, bp1);
            fma2(acc[i][2], ap, bp2);
            fma2(acc[i][3], ap, bp3);
        }
    }
}

__device__ __forceinline__ void store_tile(float (*As)[128], float (*Bs)[128],
                                           int lrow, int lk,
                                           float4 ra0, float4 ra1, float4 rb0, float4 rb1) {
    As[lk + 0][lrow]      = ra0.x; As[lk + 1][lrow]      = ra0.y;
    As[lk + 2][lrow]      = ra0.z; As[lk + 3][lrow]      = ra0.w;
    As[lk + 0][lrow + 64] = ra1.x; As[lk + 1][lrow + 64] = ra1.y;
    As[lk + 2][lrow + 64] = ra1.z; As[lk + 3][lrow + 64] = ra1.w;
    Bs[lk + 0][lrow]      = rb0.x; Bs[lk + 1][lrow]      = rb0.y;
    Bs[lk + 2][lrow]      = rb0.z; Bs[lk + 3][lrow]      = rb0.w;
    Bs[lk + 0][lrow + 64] = rb1.x; Bs[lk + 1][lrow + 64] = rb1.y;
    Bs[lk + 2][lrow + 64] = rb1.z; Bs[lk + 3][lrow + 64] = rb1.w;
}

template <int K>
__global__ __launch_bounds__(256)
void sgemm_tn(const float* __restrict__ A, const float* __restrict__ W,
              const float* __restrict__ bias, float* __restrict__ C) {
    constexpr int BK = 16;
    constexpr int NKT = K / BK;
    __shared__ float As[2][BK][128];
    __shared__ float Bs[2][BK][128];

    const int tid = threadIdx.x;
    const int tx = tid & 15;
    const int ty = tid >> 4;
    const int bm = blockIdx.y * 128;
    const int bn = blockIdx.x * 128;

    // Global-load mapping: row = tid/4 (+64), k-quad = (tid%4)*4 -> coalesced 64B rows
    const int lrow = tid >> 2;
    const int lk = (tid & 3) * 4;

    const float* Aptr0 = A + (size_t)(bm + lrow) * K + lk;
    const float* Aptr1 = Aptr0 + (size_t)64 * K;
    const float* Wptr0 = W + (size_t)(bn + lrow) * K + lk;
    const float* Wptr1 = Wptr0 + (size_t)64 * K;

    unsigned long long acc[8][4];
#pragma unroll
    for (int i = 0; i < 8; i++)
#pragma unroll
        for (int j = 0; j < 4; j++) acc[i][j] = 0ull;

    // prologue: tile 0
    float4 ra0 = *(const float4*)(Aptr0);
    float4 ra1 = *(const float4*)(Aptr1);
    float4 rb0 = *(const float4*)(Wptr0);
    float4 rb1 = *(const float4*)(Wptr1);
    store_tile(As[0], Bs[0], lrow, lk, ra0, ra1, rb0, rb1);
    __syncthreads();

    int buf = 0;
#pragma unroll 1
    for (int kt = 1; kt < NKT; ++kt) {
        ra0 = *(const float4*)(Aptr0 + kt * BK);
        ra1 = *(const float4*)(Aptr1 + kt * BK);
        rb0 = *(const float4*)(Wptr0 + kt * BK);
        rb1 = *(const float4*)(Wptr1 + kt * BK);
        tile_mma(As[buf], Bs[buf], tx, ty, acc);
        store_tile(As[buf ^ 1], Bs[buf ^ 1], lrow, lk, ra0, ra1, rb0, rb1);
        __syncthreads();
        buf ^= 1;
    }
    tile_mma(As[buf], Bs[buf], tx, ty, acc);

    // epilogue: add bias, write C (row-major, stride HID)
    const float4 bv0 = *(const float4*)&bias[bn + tx * 4];
    const float4 bv1 = *(const float4*)&bias[bn + 64 + tx * 4];
#pragma unroll
    for (int i = 0; i < 8; i++) {
        const int row = bm + ((i < 4) ? (ty * 4 + i) : (64 + ty * 4 + (i - 4)));
        const float2 c0 = unpack2(acc[i][0]);
        const float2 c1 = unpack2(acc[i][1]);
        const float2 c2 = unpack2(acc[i][2]);
        const float2 c3 = unpack2(acc[i][3]);
        float4 o0 = make_float4(c0.x + bv0.x, c0.y + bv0.y, c1.x + bv0.z, c1.y + bv0.w);
        float4 o1 = make_float4(c2.x + bv1.x, c2.y + bv1.y, c3.x + bv1.z, c3.y + bv1.w);
        *(float4*)&C[(size_t)row * HID + bn + tx * 4]      = o0;
        *(float4*)&C[(size_t)row * HID + bn + 64 + tx * 4] = o1;
    }
}

// ---------------------------------------------------------------------------
// IndRNN scan: per channel c (=b*HID+h), h[s] = relu6(lin[s] + rec*h[s-1]).
// relu6(v) = 6*saturate(v/6) -> single FFMA.SAT dependent op per step.
// Software-pipelined: block i+1's 16 loads are issued BEFORE block i's
// dependent chain, hiding DRAM latency behind the serial FFMA chain + stores.
// Only ~3.5 warps/SM (CH=16384 threads), so exposed latency is the enemy.
// ---------------------------------------------------------------------------
#define SCAN_U 16
__global__ __launch_bounds__(256)
void indrnn_scan(const float* __restrict__ lin, const float* __restrict__ rec,
                 float* __restrict__ y, float* __restrict__ h_out) {
    const int c = blockIdx.x * blockDim.x + threadIdx.x;  // 0..CH-1
    const float r = __ldg(&rec[c & (HID - 1)]);
    const float inv6 = 1.0f / 6.0f;
    float g = 0.0f;

    float v[SCAN_U], vn[SCAN_U];
    // prologue: load block 0
#pragma unroll
    for (int u = 0; u < SCAN_U; u++)
        v[u] = lin[(size_t)u * CH + c];

#pragma unroll 1
    for (int s0 = 0; s0 < SEQ - SCAN_U; s0 += SCAN_U) {
        // issue next block's loads first (latency overlaps the chain below)
#pragma unroll
        for (int u = 0; u < SCAN_U; u++)
            vn[u] = lin[(size_t)(s0 + SCAN_U + u) * CH + c];
        // dependent chain + stores for current block
#pragma unroll
        for (int u = 0; u < SCAN_U; u++) {
            g = __saturatef(fmaf(r, g, v[u] * inv6));  // FFMA.SAT
            y[(size_t)(s0 + u) * CH + c] = 6.0f * g;
        }
#pragma unroll
        for (int u = 0; u < SCAN_U; u++) v[u] = vn[u];
    }
    // epilogue: last block
#pragma unroll
    for (int u = 0; u < SCAN_U; u++) {
        g = __saturatef(fmaf(r, g, v[u] * inv6));
        y[(size_t)(SEQ - SCAN_U + u) * CH + c] = 6.0f * g;
    }
    h_out[c] = 6.0f * g;
}

// ---------------------------------------------------------------------------
// kernel_launch: GEMM0 -> scan0 -> GEMM1 -> scan1
// Output layout: [ y1 (SEQ,BATCH,HID) | h_last0 (BATCH,HID) | h_last1 (BATCH,HID) ]
// ---------------------------------------------------------------------------
extern "C" void kernel_launch(void* const* d_in, const int* in_sizes, int n_in,
                              void* d_out, int out_size) {
    (void)in_sizes; (void)n_in; (void)out_size;
    const float* x    = (const float*)d_in[0];
    const float* W0   = (const float*)d_in[1];
    const float* b0   = (const float*)d_in[2];
    const float* rec0 = (const float*)d_in[3];
    const float* W1   = (const float*)d_in[4];
    const float* b1   = (const float*)d_in[5];
    const float* rec1 = (const float*)d_in[6];
    float* out = (float*)d_out;

    float* lin = nullptr;
    float* y0  = nullptr;
    cudaGetSymbolAddress((void**)&lin, g_lin);
    cudaGetSymbolAddress((void**)&y0,  g_y0);

    dim3 ggrid(HID / 128, MTOT / 128);  // (4, 512)
    dim3 gblock(256);

    // layer 0
    sgemm_tn<XSIZE><<<ggrid, gblock>>>(x, W0, b0, lin);
    indrnn_scan<<<CH / 256, 256>>>(lin, rec0, y0, out + OUT_ELEMS);
    // layer 1
    sgemm_tn<HID><<<ggrid, gblock>>>(y0, W1, b1, lin);
    indrnn_scan<<<CH / 256, 256>>>(lin, rec1, out, out + OUT_ELEMS + CH);
}

// round 5
// speedup vs baseline: 1.6170x; 1.6170x over previous
#include <cuda_runtime.h>
#include <cuda_bf16.h>
#include <cstdint>
#include <cstddef>

#define SEQ    2048
#define BATCH  32
#define XSIZE  256
#define HID    512
#define MTOT   (SEQ * BATCH)          // 65536 GEMM rows
#define CH     (BATCH * HID)          // 16384 recurrence channels
#define OUT_ELEMS (SEQ * BATCH * HID)

// ---------------------------------------------------------------------------
// Scratch (__device__ globals; no allocation allowed). All operands plain
// row-major bf16 [rows][K].
// ---------------------------------------------------------------------------
__device__ float g_lin[OUT_ELEMS];
__device__ __nv_bfloat16 g_xhi[(size_t)MTOT * XSIZE], g_xlo[(size_t)MTOT * XSIZE];
__device__ __nv_bfloat16 g_yhi[(size_t)MTOT * HID],  g_ylo[(size_t)MTOT * HID];
__device__ __nv_bfloat16 g_w0hi[HID * XSIZE], g_w0lo[HID * XSIZE];
__device__ __nv_bfloat16 g_w1hi[HID * HID],  g_w1lo[HID * HID];

// ---------------------------------------------------------------------------
// PTX helpers (sm_80-class only: mma.sync / ldmatrix / cp.async — all legal
// on plain sm_100; tcgen05 is sm_100a-gated and the harness builds compute_100)
// ---------------------------------------------------------------------------
__device__ __forceinline__ uint32_t smem_u32(const void* p) {
    uint32_t a;
    asm("{ .reg .u64 t; cvta.to.shared.u64 t, %1; cvt.u32.u64 %0, t; }" : "=r"(a) : "l"(p));
    return a;
}
__device__ __forceinline__ void cp16(uint32_t s, const void* g) {
    asm volatile("cp.async.cg.shared.global [%0], [%1], 16;" :: "r"(s), "l"(g));
}
__device__ __forceinline__ void cp_commit() {
    asm volatile("cp.async.commit_group;" ::: "memory");
}
template <int N>
__device__ __forceinline__ void cp_wait() {
    asm volatile("cp.async.wait_group %0;" :: "n"(N) : "memory");
}
__device__ __forceinline__ void ldsm4(uint32_t* r, uint32_t a) {
    asm volatile("ldmatrix.sync.aligned.m8n8.x4.shared.b16 {%0,%1,%2,%3}, [%4];"
                 : "=r"(r[0]), "=r"(r[1]), "=r"(r[2]), "=r"(r[3]) : "r"(a));
}
__device__ __forceinline__ void mma16816(float* d, const uint32_t* a, uint32_t b0, uint32_t b1) {
    asm volatile("mma.sync.aligned.m16n8k16.row.col.f32.bf16.bf16.f32 "
                 "{%0,%1,%2,%3}, {%4,%5,%6,%7}, {%8,%9}, {%0,%1,%2,%3};"
                 : "+f"(d[0]), "+f"(d[1]), "+f"(d[2]), "+f"(d[3])
                 : "r"(a[0]), "r"(a[1]), "r"(a[2]), "r"(a[3]), "r"(b0), "r"(b1));
}

// 128B-line XOR swizzle for a [128 rows][32 bf16] tile (64B rows, 4x16B
// chunks/row). Unit = 16B. Conflict-free for cp.async stores and all
// ldmatrix phases (8 rows x same chunk -> 8 distinct bank groups).
__device__ __forceinline__ uint32_t swz(int r, int c) {
    return ((r >> 1) << 3) + ((((r & 1) << 2) + c) ^ ((r >> 1) & 7));
}

// ---------------------------------------------------------------------------
// convert fp32 -> bf16 hi/lo, plain row-major (vectorized x4)
// ---------------------------------------------------------------------------
__global__ __launch_bounds__(256)
void convert_split(const float4* __restrict__ src,
                   __nv_bfloat162* __restrict__ hi, __nv_bfloat162* __restrict__ lo) {
    const size_t i = (size_t)blockIdx.x * 256 + threadIdx.x;
    const float4 v = src[i];
    __nv_bfloat16 h0 = __float2bfloat16(v.x), h1 = __float2bfloat16(v.y);
    __nv_bfloat16 h2 = __float2bfloat16(v.z), h3 = __float2bfloat16(v.w);
    __nv_bfloat162 ph0; ph0.x = h0; ph0.y = h1;
    __nv_bfloat162 ph1; ph1.x = h2; ph1.y = h3;
    __nv_bfloat162 pl0; pl0.x = __float2bfloat16(v.x - __bfloat162float(h0));
    pl0.y = __float2bfloat16(v.y - __bfloat162float(h1));
    __nv_bfloat162 pl1; pl1.x = __float2bfloat16(v.z - __bfloat162float(h2));
    pl1.y = __float2bfloat16(v.w - __bfloat162float(h3));
    hi[i * 2] = ph0; hi[i * 2 + 1] = ph1;
    lo[i * 2] = pl0; lo[i * 2 + 1] = pl1;
}

// ---------------------------------------------------------------------------
// bf16x3 warp-MMA GEMM: C[m][n] = sum_k A[m][k]*W[n][k] + bias[n]
// 128x128x32 CTA tile, 3-stage cp.async pipeline, 8 warps (2m x 4n),
// warp tile 64x32. Same fp32 accumulators across all 3 split passes.
// ---------------------------------------------------------------------------
#define STG_BYTES 32768              // Ahi|Alo|Bhi|Blo, 8KB each
template <int K>
__global__ __launch_bounds__(256, 1)
void gemm_mma3(const __nv_bfloat16* __restrict__ Ahi, const __nv_bfloat16* __restrict__ Alo,
               const __nv_bfloat16* __restrict__ Whi, const __nv_bfloat16* __restrict__ Wlo,
               const float* __restrict__ bias, float* __restrict__ C) {
    constexpr int NKT = K / 32;
    extern __shared__ char smc[];
    const uint32_t sb = smem_u32(smc);
    const int tid = threadIdx.x, lane = tid & 31, wid = tid >> 5;
    const int bm = blockIdx.y << 7, bn = blockIdx.x << 7;
    const int m0 = (wid & 1) << 6, n0 = (wid >> 1) << 5;

    // cp.async mapping: thread -> rows (r, r+64), 16B chunk c
    const int r = tid >> 2, c = tid & 3;
    const __nv_bfloat16* gAh = Ahi + (size_t)(bm + r) * K + c * 8;
    const __nv_bfloat16* gAl = Alo + (size_t)(bm + r) * K + c * 8;
    const __nv_bfloat16* gBh = Whi + (size_t)(bn + r) * K + c * 8;
    const __nv_bfloat16* gBl = Wlo + (size_t)(bn + r) * K + c * 8;
    const uint32_t s_lo = swz(r, c) * 16, s_hi = swz(r + 64, c) * 16;

    auto issue = [&](int kt, int s) {
        const uint32_t so = sb + s * STG_BYTES;
        const int ko = kt * 32;
        cp16(so + s_lo,          gAh + ko);
        cp16(so + s_hi,          gAh + (size_t)64 * K + ko);
        cp16(so + 8192  + s_lo,  gAl + ko);
        cp16(so + 8192  + s_hi,  gAl + (size_t)64 * K + ko);
        cp16(so + 16384 + s_lo,  gBh + ko);
        cp16(so + 16384 + s_hi,  gBh + (size_t)64 * K + ko);
        cp16(so + 24576 + s_lo,  gBl + ko);
        cp16(so + 24576 + s_hi,  gBl + (size_t)64 * K + ko);
        cp_commit();
    };

    float acc[4][4][4];
#pragma unroll
    for (int i = 0; i < 4; i++)
#pragma unroll
        for (int j = 0; j < 4; j++)
#pragma unroll
            for (int k = 0; k < 4; k++) acc[i][j][k] = 0.0f;

    // ldmatrix per-lane address components
    const int a_row = m0 + (lane & 15);            // + mt*16
    const int a_chk = lane >> 4;                   // + ks*2
    const int b_row = n0 + (lane & 7) + ((lane >> 4) << 3);  // + ntp*16
    const int b_chk = (lane >> 3) & 1;             // + ks*2

    issue(0, 0);
    issue(1, 1);

#pragma unroll 1
    for (int kt = 0; kt < NKT; ++kt) {
        if (kt + 2 < NKT) { issue(kt + 2, (kt + 2) % 3); cp_wait<2>(); }
        else if (kt + 1 < NKT) { cp_wait<1>(); }
        else { cp_wait<0>(); }
        __syncthreads();

        const uint32_t so = sb + (kt % 3) * STG_BYTES;
#pragma unroll
        for (int ks = 0; ks < 2; ks++) {
            uint32_t ah[4][4], al[4][4], bh[2][4], bl[2][4];
#pragma unroll
            for (int mt = 0; mt < 4; mt++) {
                const uint32_t ad = so + swz(a_row + mt * 16, ks * 2 + a_chk) * 16;
                ldsm4(ah[mt], ad);
                ldsm4(al[mt], ad + 8192);
            }
#pragma unroll
            for (int ntp = 0; ntp < 2; ntp++) {
                const uint32_t bd = so + 16384 + swz(b_row + ntp * 16, ks * 2 + b_chk) * 16;
                ldsm4(bh[ntp], bd);
                ldsm4(bl[ntp], bd + 8192);
            }
#pragma unroll
            for (int mt = 0; mt < 4; mt++)
#pragma unroll
                for (int ntp = 0; ntp < 2; ntp++) {
                    mma16816(acc[mt][ntp * 2],     ah[mt], bh[ntp][0], bh[ntp][1]);
                    mma16816(acc[mt][ntp * 2 + 1], ah[mt], bh[ntp][2], bh[ntp][3]);
                    mma16816(acc[mt][ntp * 2],     ah[mt], bl[ntp][0], bl[ntp][1]);
                    mma16816(acc[mt][ntp * 2 + 1], ah[mt], bl[ntp][2], bl[ntp][3]);
                    mma16816(acc[mt][ntp * 2],     al[mt], bh[ntp][0], bh[ntp][1]);
                    mma16816(acc[mt][ntp * 2 + 1], al[mt], bh[ntp][2], bh[ntp][3]);
                }
        }
        __syncthreads();
    }

    // epilogue: add bias, write fp32 C (stride HID)
#pragma unroll
    for (int mt = 0; mt < 4; mt++) {
        const int row0 = bm + m0 + mt * 16 + (lane >> 2);
#pragma unroll
        for (int nt = 0; nt < 4; nt++) {
            const int col = bn + n0 + nt * 8 + (lane & 3) * 2;
            const float2 bv = *(const float2*)&bias[col];
            float2 o0 = make_float2(acc[mt][nt][0] + bv.x, acc[mt][nt][1] + bv.y);
            float2 o1 = make_float2(acc[mt][nt][2] + bv.x, acc[mt][nt][3] + bv.y);
            *(float2*)&C[(size_t)row0 * HID + col] = o0;
            *(float2*)&C[(size_t)(row0 + 8) * HID + col] = o1;
        }
    }
}

// ---------------------------------------------------------------------------
// IndRNN scans (software-pipelined; relu6(v)=6*saturate(v/6) -> FFMA.SAT)
// 128 blocks x 128 threads so all 148 SMs participate.
// ---------------------------------------------------------------------------
#define SCAN_U 16

__global__ __launch_bounds__(128)
void indrnn_scan_split(const float* __restrict__ lin, const float* __restrict__ rec,
                       __nv_bfloat16* __restrict__ yhi, __nv_bfloat16* __restrict__ ylo,
                       float* __restrict__ h_out) {
    const int c = blockIdx.x * 128 + threadIdx.x;
    const float r = __ldg(&rec[c & (HID - 1)]);
    const float inv6 = 1.0f / 6.0f;
    float g = 0.0f;

    float v[SCAN_U], vn[SCAN_U];
#pragma unroll
    for (int u = 0; u < SCAN_U; u++) v[u] = lin[(size_t)u * CH + c];

#pragma unroll 1
    for (int s0 = 0; s0 < SEQ; s0 += SCAN_U) {
        if (s0 + SCAN_U < SEQ) {
#pragma unroll
            for (int u = 0; u < SCAN_U; u++)
                vn[u] = lin[(size_t)(s0 + SCAN_U + u) * CH + c];
        }
#pragma unroll
        for (int u = 0; u < SCAN_U; u++) {
            g = __saturatef(fmaf(r, g, v[u] * inv6));
            const float yv = 6.0f * g;
            const __nv_bfloat16 hi = __float2bfloat16(yv);
            const size_t idx = (size_t)(s0 + u) * CH + c;   // == row-major (m, h)
            yhi[idx] = hi;
            ylo[idx] = __float2bfloat16(yv - __bfloat162float(hi));
        }
#pragma unroll
        for (int u = 0; u < SCAN_U; u++) v[u] = vn[u];
    }
    h_out[c] = 6.0f * g;
}

__global__ __launch_bounds__(128)
void indrnn_scan(const float* __restrict__ lin, const float* __restrict__ rec,
                 float* __restrict__ y, float* __restrict__ h_out) {
    const int c = blockIdx.x * 128 + threadIdx.x;
    const float r = __ldg(&rec[c & (HID - 1)]);
    const float inv6 = 1.0f / 6.0f;
    float g = 0.0f;

    float v[SCAN_U], vn[SCAN_U];
#pragma unroll
    for (int u = 0; u < SCAN_U; u++) v[u] = lin[(size_t)u * CH + c];

#pragma unroll 1
    for (int s0 = 0; s0 < SEQ; s0 += SCAN_U) {
        if (s0 + SCAN_U < SEQ) {
#pragma unroll
            for (int u = 0; u < SCAN_U; u++)
                vn[u] = lin[(size_t)(s0 + SCAN_U + u) * CH + c];
        }
#pragma unroll
        for (int u = 0; u < SCAN_U; u++) {
            g = __saturatef(fmaf(r, g, v[u] * inv6));
            y[(size_t)(s0 + u) * CH + c] = 6.0f * g;
        }
#pragma unroll
        for (int u = 0; u < SCAN_U; u++) v[u] = vn[u];
    }
    h_out[c] = 6.0f * g;
}

// ---------------------------------------------------------------------------
// kernel_launch
// out layout: [ y1 (SEQ,BATCH,HID) | h0 (BATCH,HID) | h1 (BATCH,HID) ]
// ---------------------------------------------------------------------------
extern "C" void kernel_launch(void* const* d_in, const int* in_sizes, int n_in,
                              void* d_out, int out_size) {
    (void)in_sizes; (void)n_in; (void)out_size;
    const float* x    = (const float*)d_in[0];
    const float* W0   = (const float*)d_in[1];
    const float* b0   = (const float*)d_in[2];
    const float* rec0 = (const float*)d_in[3];
    const float* W1   = (const float*)d_in[4];
    const float* b1   = (const float*)d_in[5];
    const float* rec1 = (const float*)d_in[6];
    float* out = (float*)d_out;

    float* lin; __nv_bfloat16 *xhi, *xlo, *yhi, *ylo, *w0hi, *w0lo, *w1hi, *w1lo;
    cudaGetSymbolAddress((void**)&lin,  g_lin);
    cudaGetSymbolAddress((void**)&xhi,  g_xhi);
    cudaGetSymbolAddress((void**)&xlo,  g_xlo);
    cudaGetSymbolAddress((void**)&yhi,  g_yhi);
    cudaGetSymbolAddress((void**)&ylo,  g_ylo);
    cudaGetSymbolAddress((void**)&w0hi, g_w0hi);
    cudaGetSymbolAddress((void**)&w0lo, g_w0lo);
    cudaGetSymbolAddress((void**)&w1hi, g_w1hi);
    cudaGetSymbolAddress((void**)&w1lo, g_w1lo);

    const int SMEM_BYTES = 3 * STG_BYTES;  // 96KB
    cudaFuncSetAttribute(gemm_mma3<XSIZE>, cudaFuncAttributeMaxDynamicSharedMemorySize, SMEM_BYTES);
    cudaFuncSetAttribute(gemm_mma3<HID>,   cudaFuncAttributeMaxDynamicSharedMemorySize, SMEM_BYTES);

    dim3 ggrid(HID / 128, MTOT / 128);  // (4, 512); x-fast => N-neighbors share A in L2

    // layer 0
    convert_split<<<(size_t)MTOT * XSIZE / 1024, 256>>>(
        (const float4*)x, (__nv_bfloat162*)xhi, (__nv_bfloat162*)xlo);
    convert_split<<<HID * XSIZE / 1024, 256>>>(
        (const float4*)W0, (__nv_bfloat162*)w0hi, (__nv_bfloat162*)w0lo);
    gemm_mma3<XSIZE><<<ggrid, 256, SMEM_BYTES>>>(xhi, xlo, w0hi, w0lo, b0, lin);
    indrnn_scan_split<<<CH / 128, 128>>>(lin, rec0, yhi, ylo, out + OUT_ELEMS);

    // layer 1
    convert_split<<<HID * HID / 1024, 256>>>(
        (const float4*)W1, (__nv_bfloat162*)w1hi, (__nv_bfloat162*)w1lo);
    gemm_mma3<HID><<<ggrid, 256, SMEM_BYTES>>>(yhi, ylo, w1hi, w1lo, b1, lin);
    indrnn_scan<<<CH / 128, 128>>>(lin, rec1, out, out + OUT_ELEMS + CH);
}

// round 6
// speedup vs baseline: 2.0812x; 1.2871x over previous
#include <cuda_runtime.h>
#include <cuda_fp16.h>
#include <cstdint>
#include <cstddef>

#define SEQ    2048
#define BATCH  32
#define XSIZE  256
#define HID    512
#define MTOT   (SEQ * BATCH)          // 65536 GEMM rows
#define CH     (BATCH * HID)          // 16384 recurrence channels
#define OUT_ELEMS (SEQ * BATCH * HID)

// ---------------------------------------------------------------------------
// Scratch (__device__ globals). Row-major [rows][K].
// A-operands split fp16 hi/lo (~2^-22 repr); W-operands single fp16 (2^-11).
// ---------------------------------------------------------------------------
__device__ float g_lin[OUT_ELEMS];
__device__ __half g_xhi[(size_t)MTOT * XSIZE], g_xlo[(size_t)MTOT * XSIZE];
__device__ __half g_yhi[(size_t)MTOT * HID],  g_ylo[(size_t)MTOT * HID];
__device__ __half g_w0[HID * XSIZE];
__device__ __half g_w1[HID * HID];

// ---------------------------------------------------------------------------
// PTX helpers (sm_80-class: legal on plain sm_100 — tcgen05 is compile-gated off)
// ---------------------------------------------------------------------------
__device__ __forceinline__ uint32_t smem_u32(const void* p) {
    uint32_t a;
    asm("{ .reg .u64 t; cvta.to.shared.u64 t, %1; cvt.u32.u64 %0, t; }" : "=r"(a) : "l"(p));
    return a;
}
__device__ __forceinline__ void cp16(uint32_t s, const void* g) {
    asm volatile("cp.async.cg.shared.global [%0], [%1], 16;" :: "r"(s), "l"(g));
}
__device__ __forceinline__ void cp_commit() {
    asm volatile("cp.async.commit_group;" ::: "memory");
}
template <int N>
__device__ __forceinline__ void cp_wait() {
    asm volatile("cp.async.wait_group %0;" :: "n"(N) : "memory");
}
__device__ __forceinline__ void ldsm4(uint32_t* r, uint32_t a) {
    asm volatile("ldmatrix.sync.aligned.m8n8.x4.shared.b16 {%0,%1,%2,%3}, [%4];"
                 : "=r"(r[0]), "=r"(r[1]), "=r"(r[2]), "=r"(r[3]) : "r"(a));
}
__device__ __forceinline__ void mma16816(float* d, const uint32_t* a, uint32_t b0, uint32_t b1) {
    asm volatile("mma.sync.aligned.m16n8k16.row.col.f32.f16.f16.f32 "
                 "{%0,%1,%2,%3}, {%4,%5,%6,%7}, {%8,%9}, {%0,%1,%2,%3};"
                 : "+f"(d[0]), "+f"(d[1]), "+f"(d[2]), "+f"(d[3])
                 : "r"(a[0]), "r"(a[1]), "r"(a[2]), "r"(a[3]), "r"(b0), "r"(b1));
}

// 128B-line XOR swizzle for [128 rows][32 halfs] tiles (64B rows, 4x16B
// chunks). Unit = 16B. Conflict-free for cp.async stores + all ldmatrix phases.
__device__ __forceinline__ uint32_t swz(int r, int c) {
    return ((r >> 1) << 3) + ((((r & 1) << 2) + c) ^ ((r >> 1) & 7));
}

// ---------------------------------------------------------------------------
// converts
// ---------------------------------------------------------------------------
__global__ __launch_bounds__(256)
void convert_split(const float4* __restrict__ src,
                   __half2* __restrict__ hi, __half2* __restrict__ lo) {
    const size_t i = (size_t)blockIdx.x * 256 + threadIdx.x;
    const float4 v = src[i];
    const __half h0 = __float2half_rn(v.x), h1 = __float2half_rn(v.y);
    const __half h2 = __float2half_rn(v.z), h3 = __float2half_rn(v.w);
    __half2 ph0; ph0.x = h0; ph0.y = h1;
    __half2 ph1; ph1.x = h2; ph1.y = h3;
    __half2 pl0; pl0.x = __float2half_rn(v.x - __half2float(h0));
    pl0.y = __float2half_rn(v.y - __half2float(h1));
    __half2 pl1; pl1.x = __float2half_rn(v.z - __half2float(h2));
    pl1.y = __float2half_rn(v.w - __half2float(h3));
    hi[i * 2] = ph0; hi[i * 2 + 1] = ph1;
    lo[i * 2] = pl0; lo[i * 2 + 1] = pl1;
}

__global__ __launch_bounds__(256)
void convert_h(const float4* __restrict__ src, __half2* __restrict__ dst) {
    const size_t i = (size_t)blockIdx.x * 256 + threadIdx.x;
    const float4 v = src[i];
    __half2 p0; p0.x = __float2half_rn(v.x); p0.y = __float2half_rn(v.y);
    __half2 p1; p1.x = __float2half_rn(v.z); p1.y = __float2half_rn(v.w);
    dst[i * 2] = p0; dst[i * 2 + 1] = p1;
}

// ---------------------------------------------------------------------------
// 2-pass fp16 warp-MMA GEMM: C = (Ahi + Alo) @ W^T + bias, fp32 accum.
// 128x128x32 CTA tile, 3-stage cp.async pipeline, 8 warps (2m x 4n),
// warp tile 64x32. Shared accumulators across both passes.
// ---------------------------------------------------------------------------
#define STG_BYTES 24576              // Ahi|Alo|B, 8KB each
template <int K>
__global__ __launch_bounds__(256, 1)
void gemm_mma2(const __half* __restrict__ Ahi, const __half* __restrict__ Alo,
               const __half* __restrict__ W, const float* __restrict__ bias,
               float* __restrict__ C) {
    constexpr int NKT = K / 32;
    extern __shared__ char smc[];
    const uint32_t sb = smem_u32(smc);
    const int tid = threadIdx.x, lane = tid & 31, wid = tid >> 5;
    const int bm = blockIdx.y << 7, bn = blockIdx.x << 7;
    const int m0 = (wid & 1) << 6, n0 = (wid >> 1) << 5;

    const int r = tid >> 2, c = tid & 3;
    const __half* gAh = Ahi + (size_t)(bm + r) * K + c * 8;
    const __half* gAl = Alo + (size_t)(bm + r) * K + c * 8;
    const __half* gB  = W   + (size_t)(bn + r) * K + c * 8;
    const uint32_t s_lo = swz(r, c) * 16, s_hi = swz(r + 64, c) * 16;

    auto issue = [&](int kt, int s) {
        const uint32_t so = sb + s * STG_BYTES;
        const int ko = kt * 32;
        cp16(so + s_lo,          gAh + ko);
        cp16(so + s_hi,          gAh + (size_t)64 * K + ko);
        cp16(so + 8192  + s_lo,  gAl + ko);
        cp16(so + 8192  + s_hi,  gAl + (size_t)64 * K + ko);
        cp16(so + 16384 + s_lo,  gB + ko);
        cp16(so + 16384 + s_hi,  gB + (size_t)64 * K + ko);
        cp_commit();
    };

    float acc[4][4][4];
#pragma unroll
    for (int i = 0; i < 4; i++)
#pragma unroll
        for (int j = 0; j < 4; j++)
#pragma unroll
            for (int k = 0; k < 4; k++) acc[i][j][k] = 0.0f;

    const int a_row = m0 + (lane & 15);
    const int a_chk = lane >> 4;
    const int b_row = n0 + (lane & 7) + ((lane >> 4) << 3);
    const int b_chk = (lane >> 3) & 1;

    issue(0, 0);
    issue(1, 1);

#pragma unroll 1
    for (int kt = 0; kt < NKT; ++kt) {
        if (kt + 2 < NKT) { issue(kt + 2, (kt + 2) % 3); cp_wait<2>(); }
        else if (kt + 1 < NKT) { cp_wait<1>(); }
        else { cp_wait<0>(); }
        __syncthreads();

        const uint32_t so = sb + (kt % 3) * STG_BYTES;
#pragma unroll
        for (int ks = 0; ks < 2; ks++) {
            uint32_t ah[4][4], al[4][4], bf[2][4];
#pragma unroll
            for (int mt = 0; mt < 4; mt++) {
                const uint32_t ad = so + swz(a_row + mt * 16, ks * 2 + a_chk) * 16;
                ldsm4(ah[mt], ad);
                ldsm4(al[mt], ad + 8192);
            }
#pragma unroll
            for (int ntp = 0; ntp < 2; ntp++) {
                const uint32_t bd = so + 16384 + swz(b_row + ntp * 16, ks * 2 + b_chk) * 16;
                ldsm4(bf[ntp], bd);
            }
#pragma unroll
            for (int mt = 0; mt < 4; mt++)
#pragma unroll
                for (int ntp = 0; ntp < 2; ntp++) {
                    mma16816(acc[mt][ntp * 2],     ah[mt], bf[ntp][0], bf[ntp][1]);
                    mma16816(acc[mt][ntp * 2 + 1], ah[mt], bf[ntp][2], bf[ntp][3]);
                    mma16816(acc[mt][ntp * 2],     al[mt], bf[ntp][0], bf[ntp][1]);
                    mma16816(acc[mt][ntp * 2 + 1], al[mt], bf[ntp][2], bf[ntp][3]);
                }
        }
        __syncthreads();
    }

#pragma unroll
    for (int mt = 0; mt < 4; mt++) {
        const int row0 = bm + m0 + mt * 16 + (lane >> 2);
#pragma unroll
        for (int nt = 0; nt < 4; nt++) {
            const int col = bn + n0 + nt * 8 + (lane & 3) * 2;
            const float2 bv = *(const float2*)&bias[col];
            float2 o0 = make_float2(acc[mt][nt][0] + bv.x, acc[mt][nt][1] + bv.y);
            float2 o1 = make_float2(acc[mt][nt][2] + bv.x, acc[mt][nt][3] + bv.y);
            *(float2*)&C[(size_t)row0 * HID + col] = o0;
            *(float2*)&C[(size_t)(row0 + 8) * HID + col] = o1;
        }
    }
}

// ---------------------------------------------------------------------------
// IndRNN scans. relu6(v)=6*saturate(v/6) -> one FFMA.SAT per step.
// SCAN_U=32 doubles in-flight loads (latency-bound at occ ~6%).
// ---------------------------------------------------------------------------
#define SCAN_U 32

__global__ __launch_bounds__(128)
void indrnn_scan_split(const float* __restrict__ lin, const float* __restrict__ rec,
                       __half* __restrict__ yhi, __half* __restrict__ ylo,
                       float* __restrict__ h_out) {
    const int c = blockIdx.x * 128 + threadIdx.x;
    const float r = __ldg(&rec[c & (HID - 1)]);
    const float inv6 = 1.0f / 6.0f;
    float g = 0.0f;

    float v[SCAN_U], vn[SCAN_U];
#pragma unroll
    for (int u = 0; u < SCAN_U; u++) v[u] = lin[(size_t)u * CH + c];

#pragma unroll 1
    for (int s0 = 0; s0 < SEQ; s0 += SCAN_U) {
        if (s0 + SCAN_U < SEQ) {
#pragma unroll
            for (int u = 0; u < SCAN_U; u++)
                vn[u] = lin[(size_t)(s0 + SCAN_U + u) * CH + c];
        }
#pragma unroll
        for (int u = 0; u < SCAN_U; u++) {
            g = __saturatef(fmaf(r, g, v[u] * inv6));
            const float yv = 6.0f * g;
            const __half hi = __float2half_rn(yv);
            const size_t idx = (size_t)(s0 + u) * CH + c;
            yhi[idx] = hi;
            ylo[idx] = __float2half_rn(yv - __half2float(hi));
        }
#pragma unroll
        for (int u = 0; u < SCAN_U; u++) v[u] = vn[u];
    }
    h_out[c] = 6.0f * g;
}

__global__ __launch_bounds__(128)
void indrnn_scan(const float* __restrict__ lin, const float* __restrict__ rec,
                 float* __restrict__ y, float* __restrict__ h_out) {
    const int c = blockIdx.x * 128 + threadIdx.x;
    const float r = __ldg(&rec[c & (HID - 1)]);
    const float inv6 = 1.0f / 6.0f;
    float g = 0.0f;

    float v[SCAN_U], vn[SCAN_U];
#pragma unroll
    for (int u = 0; u < SCAN_U; u++) v[u] = lin[(size_t)u * CH + c];

#pragma unroll 1
    for (int s0 = 0; s0 < SEQ; s0 += SCAN_U) {
        if (s0 + SCAN_U < SEQ) {
#pragma unroll
            for (int u = 0; u < SCAN_U; u++)
                vn[u] = lin[(size_t)(s0 + SCAN_U + u) * CH + c];
        }
#pragma unroll
        for (int u = 0; u < SCAN_U; u++) {
            g = __saturatef(fmaf(r, g, v[u] * inv6));
            y[(size_t)(s0 + u) * CH + c] = 6.0f * g;
        }
#pragma unroll
        for (int u = 0; u < SCAN_U; u++) v[u] = vn[u];
    }
    h_out[c] = 6.0f * g;
}

// ---------------------------------------------------------------------------
// kernel_launch
// out layout: [ y1 (SEQ,BATCH,HID) | h0 (BATCH,HID) | h1 (BATCH,HID) ]
// ---------------------------------------------------------------------------
extern "C" void kernel_launch(void* const* d_in, const int* in_sizes, int n_in,
                              void* d_out, int out_size) {
    (void)in_sizes; (void)n_in; (void)out_size;
    const float* x    = (const float*)d_in[0];
    const float* W0   = (const float*)d_in[1];
    const float* b0   = (const float*)d_in[2];
    const float* rec0 = (const float*)d_in[3];
    const float* W1   = (const float*)d_in[4];
    const float* b1   = (const float*)d_in[5];
    const float* rec1 = (const float*)d_in[6];
    float* out = (float*)d_out;

    float* lin; __half *xhi, *xlo, *yhi, *ylo, *w0, *w1;
    cudaGetSymbolAddress((void**)&lin, g_lin);
    cudaGetSymbolAddress((void**)&xhi, g_xhi);
    cudaGetSymbolAddress((void**)&xlo, g_xlo);
    cudaGetSymbolAddress((void**)&yhi, g_yhi);
    cudaGetSymbolAddress((void**)&ylo, g_ylo);
    cudaGetSymbolAddress((void**)&w0,  g_w0);
    cudaGetSymbolAddress((void**)&w1,  g_w1);

    const int SMEM_BYTES = 3 * STG_BYTES;  // 72KB
    cudaFuncSetAttribute(gemm_mma2<XSIZE>, cudaFuncAttributeMaxDynamicSharedMemorySize, SMEM_BYTES);
    cudaFuncSetAttribute(gemm_mma2<HID>,   cudaFuncAttributeMaxDynamicSharedMemorySize, SMEM_BYTES);

    dim3 ggrid(HID / 128, MTOT / 128);  // (4, 512)

    // layer 0
    convert_split<<<(size_t)MTOT * XSIZE / 1024, 256>>>(
        (const float4*)x, (__half2*)xhi, (__half2*)xlo);
    convert_h<<<HID * XSIZE / 1024, 256>>>((const float4*)W0, (__half2*)w0);
    gemm_mma2<XSIZE><<<ggrid, 256, SMEM_BYTES>>>(xhi, xlo, w0, b0, lin);
    indrnn_scan_split<<<CH / 128, 128>>>(lin, rec0, yhi, ylo, out + OUT_ELEMS);

    // layer 1
    convert_h<<<HID * HID / 1024, 256>>>((const float4*)W1, (__half2*)w1);
    gemm_mma2<HID><<<ggrid, 256, SMEM_BYTES>>>(yhi, ylo, w1, b1, lin);
    indrnn_scan<<<CH / 128, 128>>>(lin, rec1, out, out + OUT_ELEMS + CH);
}